// round 4
// baseline (speedup 1.0000x reference)
#include <cuda_runtime.h>

// CBFHalfspace collapses analytically:
//   h(x) = [1+x0, 1-x0, 1+x1, 1-x1];  Lfh = Lf2h = 0, LgLfh = (0,0)  (affine h, A col-sums 0)
// Output row: [1+x0, 1-x0, 1+x1, 1-x1, 0,0,0,0]. f, g are dead inputs.
//
// R4: warp-autonomous staging (no __syncthreads).
//   Each warp owns 128 rows: stages 224 float4 of x into its PRIVATE smem slice
//   (7 coalesced LDG.128 per lane), __syncwarp, then sweeps its 256 output
//   float4s contiguously (8 coalesced STG.128 per lane). No cross-warp barrier
//   -> independent load/store pipelines across ~52 resident warps keep the DRAM
//   queue dense. Streaming cache hints (.cs) on both zero-reuse streams.

#define THREADS 256
#define WARPS (THREADS / 32)
#define ROWS_PER_WARP 128
#define ROWS_PER_BLOCK (WARPS * ROWS_PER_WARP)      // 1024
#define F4_PER_WARP (ROWS_PER_WARP * 7 / 4)         // 224
#define OUT4_PER_WARP (ROWS_PER_WARP * 2)           // 256

__global__ void __launch_bounds__(THREADS)
cbf_kernel(const float4* __restrict__ x4, float4* __restrict__ out4, int n)
{
    __shared__ float buf[ROWS_PER_BLOCK * 7];       // 28 KB, 3584 B per warp

    const int lane = threadIdx.x & 31;
    const int wid  = threadIdx.x >> 5;

    const int warpRow0 = blockIdx.x * ROWS_PER_BLOCK + wid * ROWS_PER_WARP;
    int rowsHere = n - warpRow0;
    if (rowsHere <= 0) return;
    if (rowsHere > ROWS_PER_WARP) rowsHere = ROWS_PER_WARP;
    const int f4Here = (rowsHere * 7 + 3) >> 2;

    float*  wbuf  = buf + wid * (ROWS_PER_WARP * 7);
    float4* wbufv = (float4*)wbuf;

    const long long f4Base  = (long long)warpRow0 * 7 / 4;   // warpRow0 % 4 == 0
    const long long outBase = (long long)warpRow0 * 2;

    // Phase 1: coalesced float4 stage into this warp's smem slice.
    #pragma unroll
    for (int k = 0; k < 7; k++) {
        int idx = k * 32 + lane;
        if (idx < f4Here) wbufv[idx] = __ldcs(&x4[f4Base + idx]);
    }
    __syncwarp();

    // Phase 2: contiguous sweep over this warp's output float4s.
    #pragma unroll
    for (int k = 0; k < 8; k++) {
        int idx = k * 32 + lane;                    // 0..255
        int row = idx >> 1;
        if (row < rowsHere) {
            float4 v;
            if (idx & 1) {
                v = make_float4(0.0f, 0.0f, 0.0f, 0.0f);
            } else {
                float x0 = wbuf[row * 7 + 0];
                float x1 = wbuf[row * 7 + 1];
                v = make_float4(1.0f + x0, 1.0f - x0, 1.0f + x1, 1.0f - x1);
            }
            __stcs(&out4[outBase + idx], v);
        }
    }
}

extern "C" void kernel_launch(void* const* d_in, const int* in_sizes, int n_in,
                              void* d_out, int out_size)
{
    const float4* x4 = (const float4*)d_in[0];   // (B,7) fp32; B*7 divisible by 4
    float4* out4 = (float4*)d_out;               // (B,8) fp32 = 2 float4 per row

    const int n = in_sizes[0] / 7;               // B rows
    const int blocks = (n + ROWS_PER_BLOCK - 1) / ROWS_PER_BLOCK;
    cbf_kernel<<<blocks, THREADS>>>(x4, out4, n);
}

// round 5
// speedup vs baseline: 1.1136x; 1.1136x over previous
#include <cuda_runtime.h>

// CBFHalfspace collapses analytically:
//   h(x) = [1+x0, 1-x0, 1+x1, 1-x1];  Lfh = Lf2h = 0, LgLfh = (0,0)  (affine h, A col-sums 0)
// Output row: [1+x0, 1-x0, 1+x1, 1-x1, 0,0,0,0]. f, g are dead inputs.
//
// R5: occupancy push. 64 rows/warp -> 14 KB smem/block -> 8 blocks/SM (vs 6),
// more warps in flight to densify the DRAM request stream. Warp-autonomous
// (no block barrier), branch-free fast path for full tiles, .cs streaming hints.

#define THREADS 256
#define WARPS (THREADS / 32)
#define ROWS_PER_WARP 64
#define ROWS_PER_BLOCK (WARPS * ROWS_PER_WARP)      // 512
#define F4_PER_WARP (ROWS_PER_WARP * 7 / 4)         // 112
#define OUT4_PER_WARP (ROWS_PER_WARP * 2)           // 128

__global__ void __launch_bounds__(THREADS)
cbf_kernel(const float4* __restrict__ x4, float4* __restrict__ out4, int n)
{
    __shared__ float buf[ROWS_PER_BLOCK * 7];       // 14 KB

    const int lane = threadIdx.x & 31;
    const int wid  = threadIdx.x >> 5;

    const int warpRow0 = blockIdx.x * ROWS_PER_BLOCK + wid * ROWS_PER_WARP;
    int rowsHere = n - warpRow0;
    if (rowsHere <= 0) return;

    float*  wbuf  = buf + wid * (ROWS_PER_WARP * 7);
    float4* wbufv = (float4*)wbuf;

    const long long f4Base  = (long long)warpRow0 * 7 / 4;   // warpRow0 % 4 == 0
    const long long outBase = (long long)warpRow0 * 2;

    if (rowsHere >= ROWS_PER_WARP) {
        // ---- fast path: full 64-row tile ----
        // Loads: 112 float4 = 3 full warp-iters + half iter (lane<16).
        float4 r0 = __ldcs(&x4[f4Base +  0 + lane]);
        float4 r1 = __ldcs(&x4[f4Base + 32 + lane]);
        float4 r2 = __ldcs(&x4[f4Base + 64 + lane]);
        float4 r3;
        if (lane < 16) r3 = __ldcs(&x4[f4Base + 96 + lane]);
        wbufv[ 0 + lane] = r0;
        wbufv[32 + lane] = r1;
        wbufv[64 + lane] = r2;
        if (lane < 16) wbufv[96 + lane] = r3;
        __syncwarp();

        // Stores: 128 output float4 = 4 full warp-iters, contiguous sweep.
        #pragma unroll
        for (int k = 0; k < 4; k++) {
            int idx = k * 32 + lane;                // 0..127
            int row = idx >> 1;
            float4 v;
            if (idx & 1) {
                v = make_float4(0.0f, 0.0f, 0.0f, 0.0f);
            } else {
                float x0 = wbuf[row * 7 + 0];
                float x1 = wbuf[row * 7 + 1];
                v = make_float4(1.0f + x0, 1.0f - x0, 1.0f + x1, 1.0f - x1);
            }
            __stcs(&out4[outBase + idx], v);
        }
    } else {
        // ---- tail tile (generic, predicated) ----
        const int f4Here = (rowsHere * 7 + 3) >> 2;
        #pragma unroll
        for (int k = 0; k < 4; k++) {
            int idx = k * 32 + lane;
            if (idx < f4Here) wbufv[idx] = __ldcs(&x4[f4Base + idx]);
        }
        __syncwarp();
        #pragma unroll
        for (int k = 0; k < 4; k++) {
            int idx = k * 32 + lane;
            int row = idx >> 1;
            if (row < rowsHere) {
                float4 v;
                if (idx & 1) {
                    v = make_float4(0.0f, 0.0f, 0.0f, 0.0f);
                } else {
                    float x0 = wbuf[row * 7 + 0];
                    float x1 = wbuf[row * 7 + 1];
                    v = make_float4(1.0f + x0, 1.0f - x0, 1.0f + x1, 1.0f - x1);
                }
                __stcs(&out4[outBase + idx], v);
            }
        }
    }
}

extern "C" void kernel_launch(void* const* d_in, const int* in_sizes, int n_in,
                              void* d_out, int out_size)
{
    const float4* x4 = (const float4*)d_in[0];   // (B,7) fp32; B*7 divisible by 4
    float4* out4 = (float4*)d_out;               // (B,8) fp32 = 2 float4 per row

    const int n = in_sizes[0] / 7;               // B rows
    const int blocks = (n + ROWS_PER_BLOCK - 1) / ROWS_PER_BLOCK;
    cbf_kernel<<<blocks, THREADS>>>(x4, out4, n);
}